// round 8
// baseline (speedup 1.0000x reference)
#include <cuda_runtime.h>
#include <cuda_bf16.h>
#include <math.h>

#define NN   8192
#define EE   262144
#define IND  512
#define HD1  256
#define HD2  128

// ---------------- scratch (device globals; no allocations allowed) ----------
__device__ int   g_deg_out[NN];
__device__ int   g_deg_in[NN];
__device__ float g_norm_src[NN];
__device__ float g_norm_dst[NN];
__device__ int   g_csr_off[NN + 1];
__device__ int   g_csr_pos[NN];
__device__ int   g_csr_src[EE];

__device__ __align__(128) __nv_bfloat16 g_fhi[(size_t)NN * IND];
__device__ __align__(128) __nv_bfloat16 g_flo[(size_t)NN * IND];
__device__ __align__(128) __nv_bfloat16 g_w1thi[(size_t)HD1 * IND];
__device__ __align__(128) __nv_bfloat16 g_w1tlo[(size_t)HD1 * IND];
__device__ __align__(128) __nv_bfloat16 g_w2thi[(size_t)HD2 * HD1];
__device__ __align__(128) __nv_bfloat16 g_w2tlo[(size_t)HD2 * HD1];
__device__ __align__(128) float g_y1[(size_t)NN * HD1];
__device__ __align__(128) float g_y2[(size_t)NN * HD2];
__device__ __align__(128) __nv_bfloat16 g_x1hi[(size_t)NN * HD1];
__device__ __align__(128) __nv_bfloat16 g_x1lo[(size_t)NN * HD1];
__device__ __align__(128) __nv_bfloat16 g_ehi[(size_t)NN * HD2];
__device__ __align__(128) __nv_bfloat16 g_elo[(size_t)NN * HD2];

// ---------------- cp.async helpers ------------------------------------------
__device__ __forceinline__ void cp16(void* smem, const void* g) {
    unsigned s = (unsigned)__cvta_generic_to_shared(smem);
    asm volatile("cp.async.cg.shared.global [%0], [%1], 16;" :: "r"(s), "l"(g));
}
__device__ __forceinline__ void cp_commit() {
    asm volatile("cp.async.commit_group;");
}
template<int N>
__device__ __forceinline__ void cp_wait() {
    asm volatile("cp.async.wait_group %0;" :: "n"(N));
}

// ---------------- graph preprocessing ---------------------------------------
__global__ void k_zero_deg() {
    int i = blockIdx.x * blockDim.x + threadIdx.x;
    if (i < NN) { g_deg_out[i] = 0; g_deg_in[i] = 0; }
}

__global__ void k_degrees(const int* __restrict__ src, const int* __restrict__ dst) {
    int e = blockIdx.x * blockDim.x + threadIdx.x;
    if (e < EE) {
        atomicAdd(&g_deg_out[src[e]], 1);
        atomicAdd(&g_deg_in[dst[e]], 1);
    }
}

// exclusive scan of in-degrees + norms: 1024 threads, 8 items each
__global__ void k_scan_csr_norms() {
    __shared__ int wsum[32];
    const int tid = threadIdx.x, lane = tid & 31, wid = tid >> 5;
    int4 d0 = *(const int4*)&g_deg_in[tid * 8];
    int4 d1 = *(const int4*)&g_deg_in[tid * 8 + 4];
    int v[8] = {d0.x, d0.y, d0.z, d0.w, d1.x, d1.y, d1.z, d1.w};
    int local[8];
    int s = 0;
#pragma unroll
    for (int j = 0; j < 8; j++) { local[j] = s; s += v[j]; }
    int inc = s;
#pragma unroll
    for (int d = 1; d < 32; d <<= 1) {
        int u = __shfl_up_sync(0xffffffffu, inc, d);
        if (lane >= d) inc += u;
    }
    if (lane == 31) wsum[wid] = inc;
    __syncthreads();
    if (wid == 0) {
        int w = wsum[lane];
        int i2 = w;
#pragma unroll
        for (int d = 1; d < 32; d <<= 1) {
            int u = __shfl_up_sync(0xffffffffu, i2, d);
            if (lane >= d) i2 += u;
        }
        wsum[lane] = i2 - w;   // exclusive
    }
    __syncthreads();
    int off = wsum[wid] + inc - s;
    int4 o0 = make_int4(off + local[0], off + local[1], off + local[2], off + local[3]);
    int4 o1 = make_int4(off + local[4], off + local[5], off + local[6], off + local[7]);
    *(int4*)&g_csr_off[tid * 8] = o0;
    *(int4*)&g_csr_off[tid * 8 + 4] = o1;
    *(int4*)&g_csr_pos[tid * 8] = o0;
    *(int4*)&g_csr_pos[tid * 8 + 4] = o1;
    if (tid == 0) g_csr_off[NN] = EE;

    // norms: dst from deg_in (v[]), src from deg_out
    int4 q0 = *(const int4*)&g_deg_out[tid * 8];
    int4 q1 = *(const int4*)&g_deg_out[tid * 8 + 4];
    int w8[8] = {q0.x, q0.y, q0.z, q0.w, q1.x, q1.y, q1.z, q1.w};
    float nd[8], ns[8];
#pragma unroll
    for (int j = 0; j < 8; j++) {
        nd[j] = rsqrtf(fmaxf((float)v[j], 1.f));
        ns[j] = rsqrtf(fmaxf((float)w8[j], 1.f));
    }
    *(float4*)&g_norm_dst[tid * 8]     = make_float4(nd[0], nd[1], nd[2], nd[3]);
    *(float4*)&g_norm_dst[tid * 8 + 4] = make_float4(nd[4], nd[5], nd[6], nd[7]);
    *(float4*)&g_norm_src[tid * 8]     = make_float4(ns[0], ns[1], ns[2], ns[3]);
    *(float4*)&g_norm_src[tid * 8 + 4] = make_float4(ns[4], ns[5], ns[6], ns[7]);
}

__global__ void k_csr_fill(const int* __restrict__ src, const int* __restrict__ dst) {
    int e = blockIdx.x * blockDim.x + threadIdx.x;
    if (e < EE) {
        int d = dst[e];
        int p = atomicAdd(&g_csr_pos[d], 1);
        g_csr_src[p] = src[e];
    }
}

// ---------------- prep: feature & weight bf16 splits ------------------------
__global__ void k_prep_feat(const float* __restrict__ feat) {
    int i4 = blockIdx.x * blockDim.x + threadIdx.x;
    if (i4 < (NN * IND) / 4) {
        int i = i4 * 4;
        float4 u = __ldg((const float4*)&feat[i]);
        float x[4] = {u.x, u.y, u.z, u.w};
        __nv_bfloat162 h01, h23, l01, l23;
        __nv_bfloat16 h;
#define SPLIT1(v, HH, LL) h = __float2bfloat16(v); HH = h; LL = __float2bfloat16((v) - __bfloat162float(h));
        SPLIT1(x[0], h01.x, l01.x); SPLIT1(x[1], h01.y, l01.y);
        SPLIT1(x[2], h23.x, l23.x); SPLIT1(x[3], h23.y, l23.y);
        *(uint2*)&g_fhi[i] = make_uint2(*(unsigned*)&h01, *(unsigned*)&h23);
        *(uint2*)&g_flo[i] = make_uint2(*(unsigned*)&l01, *(unsigned*)&l23);
    }
}

// fused: W1 [IND][HD1] -> w1t hi/lo [HD1][IND];  W2 [HD1][HD2] -> w2t hi/lo
__global__ void k_prep_w_both(const float* __restrict__ W1, const float* __restrict__ W2) {
    int i = blockIdx.x * blockDim.x + threadIdx.x;
    if (i < IND * HD1) {
        int k = i / HD1, n = i % HD1;
        float x = W1[i];
        __nv_bfloat16 h = __float2bfloat16(x);
        g_w1thi[(size_t)n * IND + k] = h;
        g_w1tlo[(size_t)n * IND + k] = __float2bfloat16(x - __bfloat162float(h));
    } else {
        int j = i - IND * HD1;
        if (j < HD1 * HD2) {
            int k = j / HD2, n = j % HD2;
            float x = W2[j];
            __nv_bfloat16 h = __float2bfloat16(x);
            g_w2thi[(size_t)n * HD1 + k] = h;
            g_w2tlo[(size_t)n * HD1 + k] = __float2bfloat16(x - __bfloat162float(h));
        }
    }
}

// ---------------- bf16 split-precision MMA building blocks ------------------
__device__ __forceinline__ void mma16816(float* c, const unsigned* a, const unsigned* b) {
    asm volatile(
        "mma.sync.aligned.m16n8k16.row.col.f32.bf16.bf16.f32 "
        "{%0,%1,%2,%3}, {%4,%5,%6,%7}, {%8,%9}, {%0,%1,%2,%3};"
        : "+f"(c[0]), "+f"(c[1]), "+f"(c[2]), "+f"(c[3])
        : "r"(a[0]), "r"(a[1]), "r"(a[2]), "r"(a[3]), "r"(b[0]), "r"(b[1]));
}

__device__ __forceinline__ float sigm(float x) {
    return __fdividef(1.f, 1.f + __expf(-x));
}

#define LDT 40   // smem leading dim (halfwords) for 32-col bf16 tiles

// ---------------- layer GEMM: C[M,Nc] = (Ahi+Alo) @ (Bhi+Blo)^T --------------
// 3-stage cp.async pipeline; per chunk all 3 split terms. 8 warps (2x4).
template<int MI>
__global__ __launch_bounds__(256, 2) void gemm_tc(
    const __nv_bfloat16* __restrict__ Ahi, const __nv_bfloat16* __restrict__ Alo,
    const __nv_bfloat16* __restrict__ Bhi, const __nv_bfloat16* __restrict__ Blo,
    float* __restrict__ C, int K, int Nc) {
    constexpr int BM = MI * 32;
    constexpr int ASZ = BM * LDT * 2;
    constexpr int BSZ = 128 * LDT * 2;
    constexpr int STG = 2 * ASZ + 2 * BSZ;
    extern __shared__ __align__(16) char dyn[];

    const int tid = threadIdx.x;
    const int warp = tid >> 5, lane = tid & 31;
    const int wm = warp & 1, wn = warp >> 1;
    const int g = lane >> 2, t4 = lane & 3;
    const int rowBase = blockIdx.y * BM, colBase = blockIdx.x * 128;

    float c[MI][4][4];
#pragma unroll
    for (int mi = 0; mi < MI; mi++)
#pragma unroll
        for (int nj = 0; nj < 4; nj++)
#pragma unroll
            for (int q = 0; q < 4; q++) c[mi][nj][q] = 0.f;

    const int R = K / 32;

    auto load_stage = [&](int st, int k0) {
        char* base = dyn + st * STG;
        __nv_bfloat16* sAh = (__nv_bfloat16*)base;
        __nv_bfloat16* sAl = (__nv_bfloat16*)(base + ASZ);
        __nv_bfloat16* sBh = (__nv_bfloat16*)(base + 2 * ASZ);
        __nv_bfloat16* sBl = (__nv_bfloat16*)(base + 2 * ASZ + BSZ);
#pragma unroll
        for (int i = tid; i < BM * 4; i += 256) {
            int r = i >> 2, cc = i & 3;
            size_t gidx = (size_t)(rowBase + r) * K + k0 + cc * 8;
            int so = r * LDT + cc * 8;
            cp16(&sAh[so], &Ahi[gidx]);
            cp16(&sAl[so], &Alo[gidx]);
        }
#pragma unroll
        for (int i = tid; i < 128 * 4; i += 256) {
            int r = i >> 2, cc = i & 3;
            size_t gidx = (size_t)(colBase + r) * K + k0 + cc * 8;
            int so = r * LDT + cc * 8;
            cp16(&sBh[so], &Bhi[gidx]);
            cp16(&sBl[so], &Blo[gidx]);
        }
    };

    load_stage(0, 0);
    cp_commit();
    load_stage(1, 32);
    cp_commit();

#pragma unroll 1
    for (int rr = 0; rr < R; rr++) {
        cp_wait<1>();
        __syncthreads();

        char* base = dyn + (rr % 3) * STG;
        const __nv_bfloat16* sAh = (const __nv_bfloat16*)base;
        const __nv_bfloat16* sAl = (const __nv_bfloat16*)(base + ASZ);
        const __nv_bfloat16* sBh = (const __nv_bfloat16*)(base + 2 * ASZ);
        const __nv_bfloat16* sBl = (const __nv_bfloat16*)(base + 2 * ASZ + BSZ);

#pragma unroll
        for (int ks = 0; ks < 2; ks++) {
            const int kk = ks * 16;
            unsigned bh[4][2], bl[4][2];
#pragma unroll
            for (int nj = 0; nj < 4; nj++) {
                int boff = (wn * 32 + nj * 8 + g) * LDT + kk + 2 * t4;
                bh[nj][0] = *(const unsigned*)&sBh[boff];
                bh[nj][1] = *(const unsigned*)&sBh[boff + 8];
                bl[nj][0] = *(const unsigned*)&sBl[boff];
                bl[nj][1] = *(const unsigned*)&sBl[boff + 8];
            }
#pragma unroll
            for (int mi = 0; mi < MI; mi++) {
                int aoff = (wm * (MI * 16) + mi * 16 + g) * LDT + kk + 2 * t4;
                unsigned ah[4], al[4];
                ah[0] = *(const unsigned*)&sAh[aoff];
                ah[1] = *(const unsigned*)&sAh[aoff + 8 * LDT];
                ah[2] = *(const unsigned*)&sAh[aoff + 8];
                ah[3] = *(const unsigned*)&sAh[aoff + 8 * LDT + 8];
                al[0] = *(const unsigned*)&sAl[aoff];
                al[1] = *(const unsigned*)&sAl[aoff + 8 * LDT];
                al[2] = *(const unsigned*)&sAl[aoff + 8];
                al[3] = *(const unsigned*)&sAl[aoff + 8 * LDT + 8];
#pragma unroll
                for (int nj = 0; nj < 4; nj++) {
                    mma16816(c[mi][nj], ah, bh[nj]);
                    mma16816(c[mi][nj], ah, bl[nj]);
                    mma16816(c[mi][nj], al, bh[nj]);
                }
            }
        }
        if (rr + 2 < R) {
            load_stage((rr + 2) % 3, (rr + 2) * 32);
            cp_commit();
        }
    }

#pragma unroll
    for (int mi = 0; mi < MI; mi++) {
        int r = rowBase + wm * (MI * 16) + mi * 16 + g;
#pragma unroll
        for (int nj = 0; nj < 4; nj++) {
            int ccol = colBase + wn * 32 + nj * 8 + 2 * t4;
            *(float2*)&C[(size_t)r * Nc + ccol] = make_float2(c[mi][nj][0], c[mi][nj][1]);
            *(float2*)&C[(size_t)(r + 8) * Nc + ccol] = make_float2(c[mi][nj][2], c[mi][nj][3]);
        }
    }
}

// ---------------- SpMM gather: WPN warps per destination node ----------------
template<int D, int WPN, bool ENS, bool RELU, bool NSRC, bool WF32>
__global__ void k_spmm_gather(const float* __restrict__ Y,
                              const float* __restrict__ bias,
                              float* __restrict__ outF,
                              __nv_bfloat16* __restrict__ outHi,
                              __nv_bfloat16* __restrict__ outLo) {
    int gw = (blockIdx.x * blockDim.x + threadIdx.x) >> 5;
    int lane = threadIdx.x & 31;
    int node = gw / WPN, part = gw % WPN;
    if (node >= NN) return;
    const int off = part * (D / WPN) + lane * 4;
    const int beg = g_csr_off[node], end = g_csr_off[node + 1];
    const int* sp = g_csr_src;

    float4 acc[8];
#pragma unroll
    for (int j = 0; j < 8; j++) acc[j] = make_float4(0.f, 0.f, 0.f, 0.f);

    int e = beg;
#pragma unroll 1
    for (; e + 8 <= end; e += 8) {
        int sdx[8];
        float nsv[8];
#pragma unroll
        for (int j = 0; j < 8; j++) sdx[j] = __ldg(sp + e + j);
#pragma unroll
        for (int j = 0; j < 8; j++) nsv[j] = ENS ? g_norm_src[sdx[j]] : 1.f;
#pragma unroll
        for (int j = 0; j < 8; j++) {
            float4 u = __ldg((const float4*)(Y + (size_t)sdx[j] * D + off));
            if (ENS) {
                acc[j].x = fmaf(nsv[j], u.x, acc[j].x);
                acc[j].y = fmaf(nsv[j], u.y, acc[j].y);
                acc[j].z = fmaf(nsv[j], u.z, acc[j].z);
                acc[j].w = fmaf(nsv[j], u.w, acc[j].w);
            } else {
                acc[j].x += u.x; acc[j].y += u.y; acc[j].z += u.z; acc[j].w += u.w;
            }
        }
    }
#pragma unroll 1
    for (; e < end; e++) {
        int s = __ldg(sp + e);
        float nsv = ENS ? g_norm_src[s] : 1.f;
        float4 u = __ldg((const float4*)(Y + (size_t)s * D + off));
        if (ENS) {
            acc[0].x = fmaf(nsv, u.x, acc[0].x);
            acc[0].y = fmaf(nsv, u.y, acc[0].y);
            acc[0].z = fmaf(nsv, u.z, acc[0].z);
            acc[0].w = fmaf(nsv, u.w, acc[0].w);
        } else {
            acc[0].x += u.x; acc[0].y += u.y; acc[0].z += u.z; acc[0].w += u.w;
        }
    }
    float v[4];
    v[0] = ((acc[0].x + acc[1].x) + (acc[2].x + acc[3].x)) + ((acc[4].x + acc[5].x) + (acc[6].x + acc[7].x));
    v[1] = ((acc[0].y + acc[1].y) + (acc[2].y + acc[3].y)) + ((acc[4].y + acc[5].y) + (acc[6].y + acc[7].y));
    v[2] = ((acc[0].z + acc[1].z) + (acc[2].z + acc[3].z)) + ((acc[4].z + acc[5].z) + (acc[6].z + acc[7].z));
    v[3] = ((acc[0].w + acc[1].w) + (acc[2].w + acc[3].w)) + ((acc[4].w + acc[5].w) + (acc[6].w + acc[7].w));

    const float nd = g_norm_dst[node];
    const float ns = NSRC ? g_norm_src[node] : 1.f;
    const size_t base = (size_t)node * D + off;

    __nv_bfloat162 h01, h23, l01, l23;
    float4 fout;
    float* fo = (float*)&fout;
#pragma unroll
    for (int j = 0; j < 4; j++) {
        float w = fmaf(v[j], nd, __ldg(&bias[off + j]));
        if (RELU) w = fmaxf(w, 0.f);
        fo[j] = w;
        w *= ns;
        __nv_bfloat16 h = __float2bfloat16(w);
        __nv_bfloat16 l = __float2bfloat16(w - __bfloat162float(h));
        if (j == 0) { h01.x = h; l01.x = l; }
        if (j == 1) { h01.y = h; l01.y = l; }
        if (j == 2) { h23.x = h; l23.x = l; }
        if (j == 3) { h23.y = h; l23.y = l; }
    }
    if (WF32) *(float4*)&outF[base] = fout;
    *(uint2*)&outHi[base] = make_uint2(*(unsigned*)&h01, *(unsigned*)&h23);
    *(uint2*)&outLo[base] = make_uint2(*(unsigned*)&l01, *(unsigned*)&l23);
}

// ================ reconstruction: logits = sigmoid(emb @ emb^T) ==============
// 256x128 tiles, 512 threads (4x4 warps), 1 CTA/SM, triangular pair-row launch.
// Tile rows = [256*bi, 256*bi+256), cols = [128*bj, +128), bj in [2bi, 63].
// Edge tiles contain diagonal/below-diagonal 128-blocks handled by guards.
__global__ __launch_bounds__(512, 1) void gemm_sym_sigmoid(float* __restrict__ L) {
    constexpr int ASZ = 256 * LDT * 2;   // 20480 bytes per 256-row tile
    constexpr int BSZ = 128 * LDT * 2;   // 10240
    constexpr int STG = 2 * ASZ + 2 * BSZ;  // 61440 per stage
    extern __shared__ __align__(16) char dyn[];
    float* tb = (float*)dyn;   // 128*132 floats = 67584B, reused after MMA

    const int t = blockIdx.x;
    // count(bi') = bi'*(65-bi'); find bi with count(bi) <= t < count(bi+1)
    int bi = (int)((65.0f - sqrtf(fmaxf(4225.0f - 4.0f * (float)t, 0.f))) * 0.5f);
    if (bi < 0) bi = 0;
    if (bi > 31) bi = 31;
    while (bi > 0 && bi * (65 - bi) > t) bi--;
    while (bi < 31 && (bi + 1) * (64 - bi) <= t) bi++;
    const int bj = 2 * bi + (t - bi * (65 - bi));
    const int rowBase = bi * 256, colBase = bj * 128;

    const int tid = threadIdx.x;
    const int warp = tid >> 5, lane = tid & 31;
    const int wm = warp & 3, wn = warp >> 2;   // 4x4 warp grid; warptile 64x32
    const int g = lane >> 2, t4 = lane & 3;

    float c[4][4][4];
#pragma unroll
    for (int mi = 0; mi < 4; mi++)
#pragma unroll
        for (int nj = 0; nj < 4; nj++)
#pragma unroll
            for (int q = 0; q < 4; q++) c[mi][nj][q] = 0.f;

    auto load_stage = [&](int st, int k0) {
        char* base = dyn + st * STG;
        __nv_bfloat16* sAh = (__nv_bfloat16*)base;
        __nv_bfloat16* sAl = (__nv_bfloat16*)(base + ASZ);
        __nv_bfloat16* sBh = (__nv_bfloat16*)(base + 2 * ASZ);
        __nv_bfloat16* sBl = (__nv_bfloat16*)(base + 2 * ASZ + BSZ);
#pragma unroll
        for (int i = tid; i < 256 * 4; i += 512) {
            int r = i >> 2, cc = i & 3;
            size_t ga = (size_t)(rowBase + r) * HD2 + k0 + cc * 8;
            int so = r * LDT + cc * 8;
            cp16(&sAh[so], &g_ehi[ga]);
            cp16(&sAl[so], &g_elo[ga]);
        }
#pragma unroll
        for (int i = tid; i < 128 * 4; i += 512) {
            int r = i >> 2, cc = i & 3;
            size_t gb = (size_t)(colBase + r) * HD2 + k0 + cc * 8;
            int so = r * LDT + cc * 8;
            cp16(&sBh[so], &g_ehi[gb]);
            cp16(&sBl[so], &g_elo[gb]);
        }
    };

    load_stage(0, 0);
    cp_commit();

#pragma unroll 1
    for (int rr = 0; rr < 4; rr++) {
        if (rr < 3) {
            load_stage((rr + 1) & 1, (rr + 1) * 32);
            cp_commit();
            cp_wait<1>();
        } else {
            cp_wait<0>();
        }
        __syncthreads();

        char* base = dyn + (rr & 1) * STG;
        const __nv_bfloat16* sAh = (const __nv_bfloat16*)base;
        const __nv_bfloat16* sAl = (const __nv_bfloat16*)(base + ASZ);
        const __nv_bfloat16* sBh = (const __nv_bfloat16*)(base + 2 * ASZ);
        const __nv_bfloat16* sBl = (const __nv_bfloat16*)(base + 2 * ASZ + BSZ);

#pragma unroll
        for (int ks = 0; ks < 2; ks++) {
            const int kk = ks * 16;
            unsigned bh[4][2], bl[4][2];
#pragma unroll
            for (int nj = 0; nj < 4; nj++) {
                int boff = (wn * 32 + nj * 8 + g) * LDT + kk + 2 * t4;
                bh[nj][0] = *(const unsigned*)&sBh[boff];
                bh[nj][1] = *(const unsigned*)&sBh[boff + 8];
                bl[nj][0] = *(const unsigned*)&sBl[boff];
                bl[nj][1] = *(const unsigned*)&sBl[boff + 8];
            }
#pragma unroll
            for (int mi = 0; mi < 4; mi++) {
                int aoff = (wm * 64 + mi * 16 + g) * LDT + kk + 2 * t4;
                unsigned ah[4], al[4];
                ah[0] = *(const unsigned*)&sAh[aoff];
                ah[1] = *(const unsigned*)&sAh[aoff + 8 * LDT];
                ah[2] = *(const unsigned*)&sAh[aoff + 8];
                ah[3] = *(const unsigned*)&sAh[aoff + 8 * LDT + 8];
                al[0] = *(const unsigned*)&sAl[aoff];
                al[1] = *(const unsigned*)&sAl[aoff + 8 * LDT];
                al[2] = *(const unsigned*)&sAl[aoff + 8];
                al[3] = *(const unsigned*)&sAl[aoff + 8 * LDT + 8];
#pragma unroll
                for (int nj = 0; nj < 4; nj++) {
                    mma16816(c[mi][nj], ah, bh[nj]);
                    mma16816(c[mi][nj], ah, bl[nj]);
                    mma16816(c[mi][nj], al, bh[nj]);
                }
            }
        }
        __syncthreads();
    }

    // sigmoid
#pragma unroll
    for (int mi = 0; mi < 4; mi++)
#pragma unroll
        for (int nj = 0; nj < 4; nj++)
#pragma unroll
            for (int q = 0; q < 4; q++) c[mi][nj][q] = sigm(c[mi][nj][q]);

    // direct-orientation stores: each warp owns 64 rows; its 128-block index:
    const int rbw = 2 * bi + (wm >> 1);
    if (bj >= rbw) {
#pragma unroll
        for (int mi = 0; mi < 4; mi++) {
            int r = rowBase + wm * 64 + mi * 16 + g;
#pragma unroll
            for (int nj = 0; nj < 4; nj++) {
                int ccol = colBase + wn * 32 + nj * 8 + 2 * t4;
                *(float2*)&L[(size_t)r * NN + ccol] = make_float2(c[mi][nj][0], c[mi][nj][1]);
                *(float2*)&L[(size_t)(r + 8) * NN + ccol] = make_float2(c[mi][nj][2], c[mi][nj][3]);
            }
        }
    }

    // mirrored stores per 128-row half h: target (colBase, rowBase + 128h)
#pragma unroll 1
    for (int h = 0; h < 2; h++) {
        if (bj <= 2 * bi + h) continue;   // only strictly-upper blocks mirror
        __syncthreads();
        if ((wm >> 1) == h) {
#pragma unroll
            for (int mi = 0; mi < 4; mi++) {
                int rr = (wm & 1) * 64 + mi * 16 + g;
#pragma unroll
                for (int nj = 0; nj < 4; nj++) {
                    int cc = wn * 32 + nj * 8 + 2 * t4;
                    tb[cc * 132 + rr]           = c[mi][nj][0];
                    tb[(cc + 1) * 132 + rr]     = c[mi][nj][1];
                    tb[cc * 132 + rr + 8]       = c[mi][nj][2];
                    tb[(cc + 1) * 132 + rr + 8] = c[mi][nj][3];
                }
            }
        }
        __syncthreads();
#pragma unroll 4
        for (int i = tid; i < 128 * 32; i += 512) {
            int r2 = i >> 5, c4 = i & 31;
            float4 v = *(float4*)&tb[r2 * 132 + c4 * 4];
            *(float4*)&L[(size_t)(colBase + r2) * NN + rowBase + h * 128 + c4 * 4] = v;
        }
    }
}

// ---------------- launch ------------------------------------------------------
extern "C" void kernel_launch(void* const* d_in, const int* in_sizes, int n_in,
                              void* d_out, int out_size) {
    const float* feat = (const float*)d_in[0];
    const int*   src  = (const int*)d_in[1];
    const int*   dst  = (const int*)d_in[2];
    const float* W1   = (const float*)d_in[3];
    const float* b1   = (const float*)d_in[4];
    const float* W2   = (const float*)d_in[5];
    const float* b2   = (const float*)d_in[6];

    float* out    = (float*)d_out;
    float* emb    = out;                       // [NN, HD2]
    float* logits = out + (size_t)NN * HD2;    // [NN, NN]

    float *y1, *y2;
    __nv_bfloat16 *fhi, *flo, *w1thi, *w1tlo, *w2thi, *w2tlo, *x1hi, *x1lo, *ehi, *elo;
    cudaGetSymbolAddress((void**)&y1, g_y1);
    cudaGetSymbolAddress((void**)&y2, g_y2);
    cudaGetSymbolAddress((void**)&fhi, g_fhi);
    cudaGetSymbolAddress((void**)&flo, g_flo);
    cudaGetSymbolAddress((void**)&w1thi, g_w1thi);
    cudaGetSymbolAddress((void**)&w1tlo, g_w1tlo);
    cudaGetSymbolAddress((void**)&w2thi, g_w2thi);
    cudaGetSymbolAddress((void**)&w2tlo, g_w2tlo);
    cudaGetSymbolAddress((void**)&x1hi, g_x1hi);
    cudaGetSymbolAddress((void**)&x1lo, g_x1lo);
    cudaGetSymbolAddress((void**)&ehi, g_ehi);
    cudaGetSymbolAddress((void**)&elo, g_elo);

    constexpr int SMEM_G12 = 3 * (2 * 64 * LDT * 2 + 2 * 128 * LDT * 2);   // 92160
    constexpr int SMEM_RC  = 2 * (2 * 256 * LDT * 2 + 2 * 128 * LDT * 2);  // 122880

    static cudaStream_t st1 = nullptr, st2 = nullptr, st3 = nullptr;
    static cudaEvent_t evR, evA, ev1, ev2, ev3;
    if (!st1) {
        cudaStreamCreateWithFlags(&st1, cudaStreamNonBlocking);
        cudaStreamCreateWithFlags(&st2, cudaStreamNonBlocking);
        cudaStreamCreateWithFlags(&st3, cudaStreamNonBlocking);
        cudaEventCreateWithFlags(&evR, cudaEventDisableTiming);
        cudaEventCreateWithFlags(&evA, cudaEventDisableTiming);
        cudaEventCreateWithFlags(&ev1, cudaEventDisableTiming);
        cudaEventCreateWithFlags(&ev2, cudaEventDisableTiming);
        cudaEventCreateWithFlags(&ev3, cudaEventDisableTiming);
        cudaFuncSetAttribute(gemm_tc<2>, cudaFuncAttributeMaxDynamicSharedMemorySize, SMEM_G12);
        cudaFuncSetAttribute(gemm_sym_sigmoid, cudaFuncAttributeMaxDynamicSharedMemorySize, SMEM_RC);
    }

    cudaEventRecord(evR, 0);
    // fork: weight prep (independent)
    cudaStreamWaitEvent(st2, evR, 0);
    k_prep_w_both<<<(IND * HD1 + HD1 * HD2) / 256, 256, 0, st2>>>(W1, W2);
    cudaEventRecord(ev2, st2);
    // fork: feature split (independent)
    cudaStreamWaitEvent(st3, evR, 0);
    k_prep_feat<<<(NN * IND / 4) / 256, 256, 0, st3>>>(feat);
    cudaEventRecord(ev3, st3);

    // main: degrees
    k_zero_deg<<<NN / 256, 256>>>();
    k_degrees<<<EE / 256, 256>>>(src, dst);
    cudaEventRecord(evA, 0);
    // fork: CSR build + norms (needs degrees only)
    cudaStreamWaitEvent(st1, evA, 0);
    k_scan_csr_norms<<<1, 1024, 0, st1>>>();
    k_csr_fill<<<EE / 256, 256, 0, st1>>>(src, dst);
    cudaEventRecord(ev1, st1);

    // gemm1: y1raw = x@W1 (norm_src folded into spmm1)
    cudaStreamWaitEvent(0, ev2, 0);
    cudaStreamWaitEvent(0, ev3, 0);
    gemm_tc<2><<<dim3(HD1 / 128, NN / 64), 256, SMEM_G12>>>(fhi, flo, w1thi, w1tlo, y1, IND, HD1);

    // spmm1: x1 = relu(norm_dst * sum ns[s]*y1raw[s] + b1), out scaled by ns
    cudaStreamWaitEvent(0, ev1, 0);
    k_spmm_gather<HD1, 2, true, true, true, false><<<(NN * 2 * 32) / 256, 256>>>(
        y1, b1, nullptr, x1hi, x1lo);

    gemm_tc<2><<<dim3(HD2 / 128, NN / 64), 256, SMEM_G12>>>(x1hi, x1lo, w2thi, w2tlo, y2, HD1, HD2);
    k_spmm_gather<HD2, 1, false, false, false, true><<<(NN * 32) / 256, 256>>>(
        y2, b2, emb, ehi, elo);

    // logits = sigmoid(emb @ emb^T): 256x128 tiles, triangular pair-row grid
    gemm_sym_sigmoid<<<1056, 512, SMEM_RC>>>(logits);
}

// round 10
// speedup vs baseline: 1.1214x; 1.1214x over previous
#include <cuda_runtime.h>
#include <cuda_bf16.h>
#include <math.h>

#define NN   8192
#define EE   262144
#define IND  512
#define HD1  256
#define HD2  128

// ---------------- scratch (device globals; no allocations allowed) ----------
__device__ int   g_deg_out[NN];
__device__ int   g_deg_in[NN];
__device__ float g_norm_src[NN];
__device__ float g_norm_dst[NN];
__device__ int   g_csr_off[NN + 1];
__device__ int   g_csr_pos[NN];
__device__ int   g_csr_src[EE];

__device__ __align__(128) __nv_bfloat16 g_fhi[(size_t)NN * IND];
__device__ __align__(128) __nv_bfloat16 g_flo[(size_t)NN * IND];
__device__ __align__(128) __nv_bfloat16 g_w1thi[(size_t)HD1 * IND];
__device__ __align__(128) __nv_bfloat16 g_w1tlo[(size_t)HD1 * IND];
__device__ __align__(128) __nv_bfloat16 g_w2thi[(size_t)HD2 * HD1];
__device__ __align__(128) __nv_bfloat16 g_w2tlo[(size_t)HD2 * HD1];
__device__ __align__(128) float g_y1[(size_t)NN * HD1];
__device__ __align__(128) float g_y2[(size_t)NN * HD2];
__device__ __align__(128) __nv_bfloat16 g_x1hi[(size_t)NN * HD1];
__device__ __align__(128) __nv_bfloat16 g_x1lo[(size_t)NN * HD1];
__device__ __align__(128) __nv_bfloat16 g_ehi[(size_t)NN * HD2];
__device__ __align__(128) __nv_bfloat16 g_elo[(size_t)NN * HD2];

// ---------------- cp.async / ldmatrix helpers --------------------------------
__device__ __forceinline__ void cp16(void* smem, const void* g) {
    unsigned s = (unsigned)__cvta_generic_to_shared(smem);
    asm volatile("cp.async.cg.shared.global [%0], [%1], 16;" :: "r"(s), "l"(g));
}
__device__ __forceinline__ void cp_commit() {
    asm volatile("cp.async.commit_group;");
}
template<int N>
__device__ __forceinline__ void cp_wait() {
    asm volatile("cp.async.wait_group %0;" :: "n"(N));
}
__device__ __forceinline__ unsigned smem_u32(const void* p) {
    return (unsigned)__cvta_generic_to_shared(p);
}
__device__ __forceinline__ void ldsm4(unsigned* r, unsigned addr) {
    asm volatile("ldmatrix.sync.aligned.m8n8.x4.shared.b16 {%0,%1,%2,%3}, [%4];"
                 : "=r"(r[0]), "=r"(r[1]), "=r"(r[2]), "=r"(r[3]) : "r"(addr));
}

// ---------------- graph preprocessing ---------------------------------------
__global__ void k_zero_deg() {
    int i = blockIdx.x * blockDim.x + threadIdx.x;
    if (i < NN) { g_deg_out[i] = 0; g_deg_in[i] = 0; }
}

__global__ void k_degrees(const int* __restrict__ src, const int* __restrict__ dst) {
    int e = blockIdx.x * blockDim.x + threadIdx.x;
    if (e < EE) {
        atomicAdd(&g_deg_out[src[e]], 1);
        atomicAdd(&g_deg_in[dst[e]], 1);
    }
}

__global__ void k_norms() {
    int i = blockIdx.x * blockDim.x + threadIdx.x;
    if (i < NN) {
        g_norm_src[i] = rsqrtf(fmaxf((float)g_deg_out[i], 1.f));
        g_norm_dst[i] = rsqrtf(fmaxf((float)g_deg_in[i], 1.f));
    }
}

// exclusive scan of in-degrees: 1024 threads, 8 items each, int4-coalesced
__global__ void k_scan_csr() {
    __shared__ int wsum[32];
    const int tid = threadIdx.x, lane = tid & 31, wid = tid >> 5;
    int4 d0 = *(const int4*)&g_deg_in[tid * 8];
    int4 d1 = *(const int4*)&g_deg_in[tid * 8 + 4];
    int v[8] = {d0.x, d0.y, d0.z, d0.w, d1.x, d1.y, d1.z, d1.w};
    int local[8];
    int s = 0;
#pragma unroll
    for (int j = 0; j < 8; j++) { local[j] = s; s += v[j]; }
    int inc = s;
#pragma unroll
    for (int d = 1; d < 32; d <<= 1) {
        int u = __shfl_up_sync(0xffffffffu, inc, d);
        if (lane >= d) inc += u;
    }
    if (lane == 31) wsum[wid] = inc;
    __syncthreads();
    if (wid == 0) {
        int w = wsum[lane];
        int i2 = w;
#pragma unroll
        for (int d = 1; d < 32; d <<= 1) {
            int u = __shfl_up_sync(0xffffffffu, i2, d);
            if (lane >= d) i2 += u;
        }
        wsum[lane] = i2 - w;   // exclusive
    }
    __syncthreads();
    int off = wsum[wid] + inc - s;
    int4 o0 = make_int4(off + local[0], off + local[1], off + local[2], off + local[3]);
    int4 o1 = make_int4(off + local[4], off + local[5], off + local[6], off + local[7]);
    *(int4*)&g_csr_off[tid * 8] = o0;
    *(int4*)&g_csr_off[tid * 8 + 4] = o1;
    *(int4*)&g_csr_pos[tid * 8] = o0;
    *(int4*)&g_csr_pos[tid * 8 + 4] = o1;
    if (tid == 0) g_csr_off[NN] = EE;
}

__global__ void k_csr_fill(const int* __restrict__ src, const int* __restrict__ dst) {
    int e = blockIdx.x * blockDim.x + threadIdx.x;
    if (e < EE) {
        int d = dst[e];
        int p = atomicAdd(&g_csr_pos[d], 1);
        g_csr_src[p] = src[e];
    }
}

// ---------------- prep: feature & weight bf16 splits ------------------------
__global__ void k_prep_feat(const float* __restrict__ feat) {
    int i4 = blockIdx.x * blockDim.x + threadIdx.x;
    if (i4 < (NN * IND) / 4) {
        int i = i4 * 4;
        int node = i >> 9;   // IND = 512
        float ns = g_norm_src[node];
        float4 u = __ldg((const float4*)&feat[i]);
        float x[4] = {u.x * ns, u.y * ns, u.z * ns, u.w * ns};
        __nv_bfloat162 h01, h23, l01, l23;
        __nv_bfloat16 h;
#define SPLIT1(v, HH, LL) h = __float2bfloat16(v); HH = h; LL = __float2bfloat16((v) - __bfloat162float(h));
        SPLIT1(x[0], h01.x, l01.x); SPLIT1(x[1], h01.y, l01.y);
        SPLIT1(x[2], h23.x, l23.x); SPLIT1(x[3], h23.y, l23.y);
        *(uint2*)&g_fhi[i] = make_uint2(*(unsigned*)&h01, *(unsigned*)&h23);
        *(uint2*)&g_flo[i] = make_uint2(*(unsigned*)&l01, *(unsigned*)&l23);
    }
}

// fused: W1 [IND][HD1] -> w1t hi/lo [HD1][IND];  W2 [HD1][HD2] -> w2t hi/lo
__global__ void k_prep_w_both(const float* __restrict__ W1, const float* __restrict__ W2) {
    int i = blockIdx.x * blockDim.x + threadIdx.x;
    if (i < IND * HD1) {
        int k = i / HD1, n = i % HD1;
        float x = W1[i];
        __nv_bfloat16 h = __float2bfloat16(x);
        g_w1thi[(size_t)n * IND + k] = h;
        g_w1tlo[(size_t)n * IND + k] = __float2bfloat16(x - __bfloat162float(h));
    } else {
        int j = i - IND * HD1;
        if (j < HD1 * HD2) {
            int k = j / HD2, n = j % HD2;
            float x = W2[j];
            __nv_bfloat16 h = __float2bfloat16(x);
            g_w2thi[(size_t)n * HD1 + k] = h;
            g_w2tlo[(size_t)n * HD1 + k] = __float2bfloat16(x - __bfloat162float(h));
        }
    }
}

// ---------------- bf16 split-precision MMA building blocks ------------------
__device__ __forceinline__ void mma16816(float* c, const unsigned* a, const unsigned* b) {
    asm volatile(
        "mma.sync.aligned.m16n8k16.row.col.f32.bf16.bf16.f32 "
        "{%0,%1,%2,%3}, {%4,%5,%6,%7}, {%8,%9}, {%0,%1,%2,%3};"
        : "+f"(c[0]), "+f"(c[1]), "+f"(c[2]), "+f"(c[3])
        : "r"(a[0]), "r"(a[1]), "r"(a[2]), "r"(a[3]), "r"(b[0]), "r"(b[1]));
}

__device__ __forceinline__ float sigm(float x) {
    return __fdividef(1.f, 1.f + __expf(-x));
}

#define LDT 40   // smem leading dim (halfwords) for 32-col bf16 tiles

// ---------------- layer GEMM: C[M,Nc] = (Ahi+Alo) @ (Bhi+Blo)^T --------------
// cp.async double-buffered; ldmatrix fragment loads; 8 warps (2x4).
template<int MI>
__global__ __launch_bounds__(256, 2) void gemm_tc(
    const __nv_bfloat16* __restrict__ Ahi, const __nv_bfloat16* __restrict__ Alo,
    const __nv_bfloat16* __restrict__ Bhi, const __nv_bfloat16* __restrict__ Blo,
    float* __restrict__ C, int K, int Nc) {
    constexpr int BM = MI * 32;
    constexpr int ASZ = BM * LDT * 2;
    constexpr int BSZ = 128 * LDT * 2;
    constexpr int STG = 2 * ASZ + 2 * BSZ;
    extern __shared__ __align__(16) char dyn[];

    const int tid = threadIdx.x;
    const int warp = tid >> 5, lane = tid & 31;
    const int wm = warp & 1, wn = warp >> 1;
    const int rowBase = blockIdx.y * BM, colBase = blockIdx.x * 128;

    // ldmatrix lane address offsets
    const int lrA = (lane & 7) + ((lane >> 3) & 1) * 8;
    const int lcA = (lane >> 4) * 8;
    const int lrB = (lane & 7) + (lane >> 4) * 8;
    const int lcB = ((lane >> 3) & 1) * 8;

    float c[MI][4][4];
#pragma unroll
    for (int mi = 0; mi < MI; mi++)
#pragma unroll
        for (int nj = 0; nj < 4; nj++)
#pragma unroll
            for (int q = 0; q < 4; q++) c[mi][nj][q] = 0.f;

    const int R = K / 32;

    auto load_stage = [&](int st, int k0) {
        char* base = dyn + st * STG;
        __nv_bfloat16* sAh = (__nv_bfloat16*)base;
        __nv_bfloat16* sAl = (__nv_bfloat16*)(base + ASZ);
        __nv_bfloat16* sBh = (__nv_bfloat16*)(base + 2 * ASZ);
        __nv_bfloat16* sBl = (__nv_bfloat16*)(base + 2 * ASZ + BSZ);
#pragma unroll
        for (int i = tid; i < BM * 4; i += 256) {
            int r = i >> 2, cc = i & 3;
            size_t gidx = (size_t)(rowBase + r) * K + k0 + cc * 8;
            int so = r * LDT + cc * 8;
            cp16(&sAh[so], &Ahi[gidx]);
            cp16(&sAl[so], &Alo[gidx]);
        }
#pragma unroll
        for (int i = tid; i < 128 * 4; i += 256) {
            int r = i >> 2, cc = i & 3;
            size_t gidx = (size_t)(colBase + r) * K + k0 + cc * 8;
            int so = r * LDT + cc * 8;
            cp16(&sBh[so], &Bhi[gidx]);
            cp16(&sBl[so], &Blo[gidx]);
        }
    };

    load_stage(0, 0);
    cp_commit();

#pragma unroll 1
    for (int rr = 0; rr < R; rr++) {
        if (rr + 1 < R) {
            load_stage((rr + 1) & 1, (rr + 1) * 32);
            cp_commit();
            cp_wait<1>();
        } else {
            cp_wait<0>();
        }
        __syncthreads();

        char* base = dyn + (rr & 1) * STG;
        const unsigned uAh = smem_u32(base);
        const unsigned uAl = uAh + ASZ;
        const unsigned uBh = uAh + 2 * ASZ;
        const unsigned uBl = uAh + 2 * ASZ + BSZ;

#pragma unroll
        for (int ks = 0; ks < 2; ks++) {
            const int kk = ks * 16;
            unsigned bhf[8], blf[8];
#pragma unroll
            for (int njp = 0; njp < 2; njp++) {
                unsigned off = (unsigned)(((wn * 32 + njp * 16 + lrB) * LDT + kk + lcB) * 2);
                ldsm4(&bhf[njp * 4], uBh + off);
                ldsm4(&blf[njp * 4], uBl + off);
            }
#pragma unroll
            for (int mi = 0; mi < MI; mi++) {
                unsigned offA = (unsigned)(((wm * (MI * 16) + mi * 16 + lrA) * LDT + kk + lcA) * 2);
                unsigned ahf[4], alf[4];
                ldsm4(ahf, uAh + offA);
                ldsm4(alf, uAl + offA);
#pragma unroll
                for (int nj = 0; nj < 4; nj++) {
                    mma16816(c[mi][nj], ahf, &bhf[nj * 2]);
                    mma16816(c[mi][nj], ahf, &blf[nj * 2]);
                    mma16816(c[mi][nj], alf, &bhf[nj * 2]);
                }
            }
        }
        __syncthreads();
    }

    const int g = lane >> 2, t4 = lane & 3;
#pragma unroll
    for (int mi = 0; mi < MI; mi++) {
        int r = rowBase + wm * (MI * 16) + mi * 16 + g;
#pragma unroll
        for (int nj = 0; nj < 4; nj++) {
            int ccol = colBase + wn * 32 + nj * 8 + 2 * t4;
            *(float2*)&C[(size_t)r * Nc + ccol] = make_float2(c[mi][nj][0], c[mi][nj][1]);
            *(float2*)&C[(size_t)(r + 8) * Nc + ccol] = make_float2(c[mi][nj][2], c[mi][nj][3]);
        }
    }
}

// ---------------- SpMM gather: WPN warps per destination node ----------------
template<int D, int WPN, bool RELU, bool NSRC, bool WF32>
__global__ void k_spmm_gather(const float* __restrict__ Y,
                              const float* __restrict__ bias,
                              float* __restrict__ outF,
                              __nv_bfloat16* __restrict__ outHi,
                              __nv_bfloat16* __restrict__ outLo) {
    int gw = (blockIdx.x * blockDim.x + threadIdx.x) >> 5;
    int lane = threadIdx.x & 31;
    int node = gw / WPN, part = gw % WPN;
    if (node >= NN) return;
    const int off = part * (D / WPN) + lane * 4;
    const int beg = g_csr_off[node], end = g_csr_off[node + 1];
    const int* sp = g_csr_src;

    float4 acc[8];
#pragma unroll
    for (int j = 0; j < 8; j++) acc[j] = make_float4(0.f, 0.f, 0.f, 0.f);

    int e = beg;
#pragma unroll 1
    for (; e + 8 <= end; e += 8) {
        int sdx[8];
#pragma unroll
        for (int j = 0; j < 8; j++) sdx[j] = __ldg(sp + e + j);
#pragma unroll
        for (int j = 0; j < 8; j++) {
            float4 u = __ldg((const float4*)(Y + (size_t)sdx[j] * D + off));
            acc[j].x += u.x; acc[j].y += u.y; acc[j].z += u.z; acc[j].w += u.w;
        }
    }
#pragma unroll 1
    for (; e < end; e++) {
        int s = __ldg(sp + e);
        float4 u = __ldg((const float4*)(Y + (size_t)s * D + off));
        acc[0].x += u.x; acc[0].y += u.y; acc[0].z += u.z; acc[0].w += u.w;
    }
    float v[4];
    v[0] = ((acc[0].x + acc[1].x) + (acc[2].x + acc[3].x)) + ((acc[4].x + acc[5].x) + (acc[6].x + acc[7].x));
    v[1] = ((acc[0].y + acc[1].y) + (acc[2].y + acc[3].y)) + ((acc[4].y + acc[5].y) + (acc[6].y + acc[7].y));
    v[2] = ((acc[0].z + acc[1].z) + (acc[2].z + acc[3].z)) + ((acc[4].z + acc[5].z) + (acc[6].z + acc[7].z));
    v[3] = ((acc[0].w + acc[1].w) + (acc[2].w + acc[3].w)) + ((acc[4].w + acc[5].w) + (acc[6].w + acc[7].w));

    const float nd = g_norm_dst[node];
    const float ns = NSRC ? g_norm_src[node] : 1.f;
    const size_t base = (size_t)node * D + off;

    __nv_bfloat162 h01, h23, l01, l23;
    float4 fout;
    float* fo = (float*)&fout;
#pragma unroll
    for (int j = 0; j < 4; j++) {
        float w = fmaf(v[j], nd, __ldg(&bias[off + j]));
        if (RELU) w = fmaxf(w, 0.f);
        fo[j] = w;
        w *= ns;
        __nv_bfloat16 h = __float2bfloat16(w);
        __nv_bfloat16 l = __float2bfloat16(w - __bfloat162float(h));
        if (j == 0) { h01.x = h; l01.x = l; }
        if (j == 1) { h01.y = h; l01.y = l; }
        if (j == 2) { h23.x = h; l23.x = l; }
        if (j == 3) { h23.y = h; l23.y = l; }
    }
    if (WF32) *(float4*)&outF[base] = fout;
    *(uint2*)&outHi[base] = make_uint2(*(unsigned*)&h01, *(unsigned*)&h23);
    *(uint2*)&outLo[base] = make_uint2(*(unsigned*)&l01, *(unsigned*)&l23);
}

// ================ reconstruction: logits = sigmoid(emb @ emb^T) ==============
// Triangular launch (2080 CTAs). cp.async double-buffered, ldmatrix fragments.
__global__ __launch_bounds__(256, 2) void gemm_sym_sigmoid(float* __restrict__ L) {
    constexpr int TSZ = 128 * LDT * 2;
    constexpr int STG = 4 * TSZ;
    extern __shared__ __align__(16) char dyn[];
    float* tb = (float*)dyn;   // 64*132 floats, reused after MMA

    const int t = blockIdx.x;
    int bi = (int)((129.0f - sqrtf(16641.0f - 8.0f * (float)t)) * 0.5f);
    while (bi * (129 - bi) / 2 > t) bi--;
    while ((bi + 1) * (128 - bi) / 2 <= t) bi++;
    const int bj = bi + (t - bi * (129 - bi) / 2);

    const int tid = threadIdx.x;
    const int warp = tid >> 5, lane = tid & 31;
    const int wm = warp & 1, wn = warp >> 1;
    const int rowBase = bi * 128, colBase = bj * 128;

    const int lrA = (lane & 7) + ((lane >> 3) & 1) * 8;
    const int lcA = (lane >> 4) * 8;
    const int lrB = (lane & 7) + (lane >> 4) * 8;
    const int lcB = ((lane >> 3) & 1) * 8;

    float c[4][4][4];
#pragma unroll
    for (int mi = 0; mi < 4; mi++)
#pragma unroll
        for (int nj = 0; nj < 4; nj++)
#pragma unroll
            for (int q = 0; q < 4; q++) c[mi][nj][q] = 0.f;

    auto load_stage = [&](int st, int k0) {
        char* base = dyn + st * STG;
        __nv_bfloat16* sAh = (__nv_bfloat16*)base;
        __nv_bfloat16* sAl = (__nv_bfloat16*)(base + TSZ);
        __nv_bfloat16* sBh = (__nv_bfloat16*)(base + 2 * TSZ);
        __nv_bfloat16* sBl = (__nv_bfloat16*)(base + 3 * TSZ);
#pragma unroll
        for (int i = tid; i < 128 * 4; i += 256) {
            int r = i >> 2, cc = i & 3;
            size_t ga = (size_t)(rowBase + r) * HD2 + k0 + cc * 8;
            size_t gb = (size_t)(colBase + r) * HD2 + k0 + cc * 8;
            int so = r * LDT + cc * 8;
            cp16(&sAh[so], &g_ehi[ga]);
            cp16(&sAl[so], &g_elo[ga]);
            cp16(&sBh[so], &g_ehi[gb]);
            cp16(&sBl[so], &g_elo[gb]);
        }
    };

    load_stage(0, 0);
    cp_commit();

#pragma unroll 1
    for (int rr = 0; rr < 4; rr++) {
        if (rr < 3) {
            load_stage((rr + 1) & 1, (rr + 1) * 32);
            cp_commit();
            cp_wait<1>();
        } else {
            cp_wait<0>();
        }
        __syncthreads();

        char* base = dyn + (rr & 1) * STG;
        const unsigned uAh = smem_u32(base);
        const unsigned uAl = uAh + TSZ;
        const unsigned uBh = uAh + 2 * TSZ;
        const unsigned uBl = uAh + 3 * TSZ;

#pragma unroll
        for (int ks = 0; ks < 2; ks++) {
            const int kk = ks * 16;
            unsigned bhf[8], blf[8];
#pragma unroll
            for (int njp = 0; njp < 2; njp++) {
                unsigned off = (unsigned)(((wn * 32 + njp * 16 + lrB) * LDT + kk + lcB) * 2);
                ldsm4(&bhf[njp * 4], uBh + off);
                ldsm4(&blf[njp * 4], uBl + off);
            }
#pragma unroll
            for (int mi = 0; mi < 4; mi++) {
                unsigned offA = (unsigned)(((wm * 64 + mi * 16 + lrA) * LDT + kk + lcA) * 2);
                unsigned ahf[4], alf[4];
                ldsm4(ahf, uAh + offA);
                ldsm4(alf, uAl + offA);
#pragma unroll
                for (int nj = 0; nj < 4; nj++) {
                    mma16816(c[mi][nj], ahf, &bhf[nj * 2]);
                    mma16816(c[mi][nj], ahf, &blf[nj * 2]);
                    mma16816(c[mi][nj], alf, &bhf[nj * 2]);
                }
            }
        }
        __syncthreads();
    }

    // sigmoid
#pragma unroll
    for (int mi = 0; mi < 4; mi++)
#pragma unroll
        for (int nj = 0; nj < 4; nj++)
#pragma unroll
            for (int q = 0; q < 4; q++) c[mi][nj][q] = sigm(c[mi][nj][q]);

    const int g = lane >> 2, t4 = lane & 3;
    // direct-orientation store
#pragma unroll
    for (int mi = 0; mi < 4; mi++) {
        int r = rowBase + wm * 64 + mi * 16 + g;
#pragma unroll
        for (int nj = 0; nj < 4; nj++) {
            int ccol = colBase + wn * 32 + nj * 8 + 2 * t4;
            *(float2*)&L[(size_t)r * NN + ccol] = make_float2(c[mi][nj][0], c[mi][nj][1]);
            *(float2*)&L[(size_t)(r + 8) * NN + ccol] = make_float2(c[mi][nj][2], c[mi][nj][3]);
        }
    }

    // mirrored store via 64-row smem transpose chunks
    if (bi != bj) {
#pragma unroll 1
        for (int ci = 0; ci < 2; ci++) {
            __syncthreads();
            if ((wn >> 1) == ci) {
#pragma unroll
                for (int mi = 0; mi < 4; mi++) {
                    int rr = wm * 64 + mi * 16 + g;
#pragma unroll
                    for (int nj = 0; nj < 4; nj++) {
                        int cc = (wn & 1) * 32 + nj * 8 + 2 * t4;
                        tb[cc * 132 + rr]           = c[mi][nj][0];
                        tb[(cc + 1) * 132 + rr]     = c[mi][nj][1];
                        tb[cc * 132 + rr + 8]       = c[mi][nj][2];
                        tb[(cc + 1) * 132 + rr + 8] = c[mi][nj][3];
                    }
                }
            }
            __syncthreads();
#pragma unroll 4
            for (int i = tid; i < 64 * 32; i += 256) {
                int r2 = i >> 5, c4 = i & 31;
                float4 v = *(float4*)&tb[r2 * 132 + c4 * 4];
                *(float4*)&L[(size_t)(colBase + ci * 64 + r2) * NN + rowBase + c4 * 4] = v;
            }
        }
    }
}

// ---------------- launch ------------------------------------------------------
extern "C" void kernel_launch(void* const* d_in, const int* in_sizes, int n_in,
                              void* d_out, int out_size) {
    const float* feat = (const float*)d_in[0];
    const int*   src  = (const int*)d_in[1];
    const int*   dst  = (const int*)d_in[2];
    const float* W1   = (const float*)d_in[3];
    const float* b1   = (const float*)d_in[4];
    const float* W2   = (const float*)d_in[5];
    const float* b2   = (const float*)d_in[6];

    float* out    = (float*)d_out;
    float* emb    = out;                       // [NN, HD2]
    float* logits = out + (size_t)NN * HD2;    // [NN, NN]

    float *y1, *y2;
    __nv_bfloat16 *fhi, *flo, *w1thi, *w1tlo, *w2thi, *w2tlo, *x1hi, *x1lo, *ehi, *elo;
    cudaGetSymbolAddress((void**)&y1, g_y1);
    cudaGetSymbolAddress((void**)&y2, g_y2);
    cudaGetSymbolAddress((void**)&fhi, g_fhi);
    cudaGetSymbolAddress((void**)&flo, g_flo);
    cudaGetSymbolAddress((void**)&w1thi, g_w1thi);
    cudaGetSymbolAddress((void**)&w1tlo, g_w1tlo);
    cudaGetSymbolAddress((void**)&w2thi, g_w2thi);
    cudaGetSymbolAddress((void**)&w2tlo, g_w2tlo);
    cudaGetSymbolAddress((void**)&x1hi, g_x1hi);
    cudaGetSymbolAddress((void**)&x1lo, g_x1lo);
    cudaGetSymbolAddress((void**)&ehi, g_ehi);
    cudaGetSymbolAddress((void**)&elo, g_elo);

    constexpr int SMEM_G1 = 2 * (2 * 128 * LDT * 2 + 2 * 128 * LDT * 2);   // 81920
    constexpr int SMEM_G2 = 2 * (2 * 64 * LDT * 2 + 2 * 128 * LDT * 2);    // 61440
    constexpr int SMEM_RC = 2 * (4 * 128 * LDT * 2);                       // 81920

    static cudaStream_t st1 = nullptr, st2 = nullptr;
    static cudaEvent_t evR, evA, ev1, ev2;
    if (!st1) {
        cudaStreamCreateWithFlags(&st1, cudaStreamNonBlocking);
        cudaStreamCreateWithFlags(&st2, cudaStreamNonBlocking);
        cudaEventCreateWithFlags(&evR, cudaEventDisableTiming);
        cudaEventCreateWithFlags(&evA, cudaEventDisableTiming);
        cudaEventCreateWithFlags(&ev1, cudaEventDisableTiming);
        cudaEventCreateWithFlags(&ev2, cudaEventDisableTiming);
        cudaFuncSetAttribute(gemm_tc<4>, cudaFuncAttributeMaxDynamicSharedMemorySize, SMEM_G1);
        cudaFuncSetAttribute(gemm_tc<2>, cudaFuncAttributeMaxDynamicSharedMemorySize, SMEM_G2);
        cudaFuncSetAttribute(gemm_sym_sigmoid, cudaFuncAttributeMaxDynamicSharedMemorySize, SMEM_RC);
    }

    // fork: weight prep runs on st2, independent of everything
    cudaEventRecord(evR, 0);
    cudaStreamWaitEvent(st2, evR, 0);
    k_prep_w_both<<<(IND * HD1 + HD1 * HD2) / 256, 256, 0, st2>>>(W1, W2);
    cudaEventRecord(ev2, st2);

    // main: degrees -> norms -> feat prep
    k_zero_deg<<<NN / 256, 256>>>();
    k_degrees<<<EE / 256, 256>>>(src, dst);
    cudaEventRecord(evA, 0);

    // fork: CSR build on st1 (needs degrees only)
    cudaStreamWaitEvent(st1, evA, 0);
    k_scan_csr<<<1, 1024, 0, st1>>>();
    k_csr_fill<<<EE / 256, 256, 0, st1>>>(src, dst);
    cudaEventRecord(ev1, st1);

    k_norms<<<NN / 256, 256>>>();
    k_prep_feat<<<(NN * IND / 4) / 256, 256>>>(feat);

    // join weights before gemm1
    cudaStreamWaitEvent(0, ev2, 0);
    gemm_tc<4><<<dim3(HD1 / 128, NN / 128), 256, SMEM_G1>>>(fhi, flo, w1thi, w1tlo, y1, IND, HD1);

    // join CSR before spmm1
    cudaStreamWaitEvent(0, ev1, 0);
    k_spmm_gather<HD1, 2, true, true, false><<<(NN * 2 * 32) / 256, 256>>>(
        y1, b1, nullptr, x1hi, x1lo);

    gemm_tc<2><<<dim3(HD2 / 128, NN / 64), 256, SMEM_G2>>>(x1hi, x1lo, w2thi, w2tlo, y2, HD1, HD2);
    k_spmm_gather<HD2, 1, false, false, true><<<(NN * 32) / 256, 256>>>(
        y2, b2, emb, ehi, elo);

    // logits = sigmoid(emb @ emb^T), triangular symmetric tensor-core GEMM
    gemm_sym_sigmoid<<<2080, 256, SMEM_RC>>>(logits);
}